// round 13
// baseline (speedup 1.0000x reference)
#include <cuda_runtime.h>
#include <cuda_fp16.h>

#define B 8
#define N 2048
#define F 64
#define MAXNNZ 256
#define BN (B*N)  // 16384
#define LRELU_SLOPE 0.2f

// ---- scratch (static device arrays; re-initialized every launch) ----
__device__ float  g_h[BN*F];                       // 4 MB fp32 h (cvec path)
__device__ __half g_hh[BN*F];                      // 2 MB fp16 h (k_out gather path)
__device__ float  g_f1[BN];
__device__ float  g_f2[BN];
__device__ float  g_Dsum[BN];                      // sum of expm1 terms per column
__device__ float  g_invD[BN];
__device__ float  g_c[B*F];                        // per-batch constant row
__device__ int    g_nnz[BN];
__device__ int    g_bcnt[B];                       // per-batch done-block counter
__device__ float2 g_pairs[(size_t)BN*MAXNNZ];      // (j as int bits, p), zero-padded to %8

// ---------------- A: h = input@W (fp32 + fp16), f1/f2, zero accumulators ----------------
__global__ void k_hproj(const float* __restrict__ in, const float* __restrict__ W,
                        const float* __restrict__ a1, const float* __restrict__ a2) {
    __shared__ float Ws[F*F];
    __shared__ float a1s[F], a2s[F];
    __shared__ float ins[8*F];
    __shared__ float hs[8*F];
    int tid = threadIdx.x;
    int rowBase = blockIdx.x * 8;

    if (blockIdx.x < 32) g_Dsum[blockIdx.x * 512 + tid] = 0.f;
    if (blockIdx.x == 32 && tid < B) g_bcnt[tid] = 0;

    for (int t = tid; t < F*F; t += 512) Ws[t] = W[t];
    if (tid < F) { a1s[tid] = a1[tid]; a2s[tid] = a2[tid]; }
    ins[tid] = in[rowBase*F + tid];
    __syncthreads();

    int r = tid >> 6, o = tid & 63;
    float acc = 0.f;
#pragma unroll
    for (int f = 0; f < F; f++) acc += ins[r*F + f] * Ws[f*F + o];
    g_h[(rowBase + r)*F + o]  = acc;
    g_hh[(rowBase + r)*F + o] = __float2half(acc);
    hs[tid] = acc;
    __syncthreads();

    int w = tid >> 5, lane = tid & 31;
    if (w < 8) {
        float v1 = hs[w*F + lane]*a1s[lane] + hs[w*F + lane + 32]*a1s[lane + 32];
        float v2 = hs[w*F + lane]*a2s[lane] + hs[w*F + lane + 32]*a2s[lane + 32];
#pragma unroll
        for (int off = 16; off; off >>= 1) {
            v1 += __shfl_down_sync(0xffffffffu, v1, off);
            v2 += __shfl_down_sync(0xffffffffu, v2, off);
        }
        if (lane == 0) { g_f1[rowBase + w] = v1; g_f2[rowBase + w] = v2; }
    }
}

// ---------------- B: two-phase scan + fused last-block cvec ----------------
// block = 512 threads = 16 warps = 16 rows; grid = BN/16 (128 blocks/batch).
__global__ void k_scan(const float* __restrict__ adj) {
    __shared__ float Dpart[N];        // 8 KB (reused as reduction scratch in tail)
    __shared__ float f2s[N];          // 8 KB (reused as invD cache in tail)
    __shared__ int   isLast;
    int tid = threadIdx.x;
    int b  = blockIdx.x >> 7;
    int i0 = (blockIdx.x & 127) * 16;

    for (int t = tid; t < N; t += 512) Dpart[t] = 0.f;
    for (int t = tid; t < N; t += 512) f2s[t] = g_f2[b*N + t];
    __syncthreads();

    int w = tid >> 5, lane = tid & 31;
    int row = b*N + i0 + w;
    float f1i = g_f1[row];
    const float4* __restrict__ arow = (const float4*)(adj + (size_t)row * N);
    float2* pbase = g_pairs + (size_t)row * MAXNNZ;
    unsigned lmask = (1u << lane) - 1u;

    // ---- phase 1: stream adj, build per-lane 64-bit nonzero mask (no warp sync) ----
    unsigned long long m64 = 0ull;
    float4 a0 = arow[lane], a1 = arow[lane + 32];
#pragma unroll 1
    for (int it = 0; it < 16; it += 2) {
        float4 n0, n1;
        if (it < 14) {
            n0 = arow[(it + 2)*32 + lane];
            n1 = arow[(it + 3)*32 + lane];
        }
        unsigned mk0 = (a0.x != 0.f ? 1u : 0u) | (a0.y != 0.f ? 2u : 0u)
                     | (a0.z != 0.f ? 4u : 0u) | (a0.w != 0.f ? 8u : 0u);
        unsigned mk1 = (a1.x != 0.f ? 1u : 0u) | (a1.y != 0.f ? 2u : 0u)
                     | (a1.z != 0.f ? 4u : 0u) | (a1.w != 0.f ? 8u : 0u);
        m64 |= ((unsigned long long)(mk0 | (mk1 << 4))) << (4*it);
        a0 = n0; a1 = n1;
    }
    int cnt = __popcll(m64);

    // ---- one prefix across lanes (cnt <= 64 -> 7 count-bit ballots) ----
    int base = 0, total = 0;
#pragma unroll
    for (int bit = 0; bit < 7; bit++) {
        unsigned mm = __ballot_sync(0xffffffffu, (cnt >> bit) & 1);
        base  += __popc(mm & lmask) << bit;
        total += __popc(mm) << bit;
    }

    // ---- phase 2: drain set bits (independent per lane) ----
    while (m64) {
        int bitp = __ffsll(m64) - 1;
        m64 &= m64 - 1;
        int it = bitp >> 2, k = bitp & 3;
        int j = ((it*32 + lane) << 2) + k;
        float e = f1i + f2s[j];
        e = (e >= 0.f) ? e : LRELU_SLOPE * e;
        float p = __expf(e) - 1.f;
        if (base < MAXNNZ)
            pbase[base] = make_float2(__int_as_float(j), p);
        base++;
        atomicAdd(&Dpart[j], p);
    }

    int nnz = min(total, MAXNNZ);
    if (lane == 0) g_nnz[row] = nnz;
    int npad = (nnz + 7) & ~7;
    if (nnz + lane < npad) pbase[nnz + lane] = make_float2(0.f, 0.f);

    __syncthreads();
    for (int tt = tid; tt < N; tt += 512) atomicAdd(&g_Dsum[b*N + tt], Dpart[tt]);

    // ---- fused cvec: last block of this batch computes invD + c ----
    __threadfence();
    if (tid == 0) isLast = (atomicAdd(&g_bcnt[b], 1) == 127);
    __syncthreads();
    if (isLast) {
        for (int t = tid; t < N; t += 512) {
            float v = 1.f / ((float)N + g_Dsum[b*N + t]);
            g_invD[b*N + t] = v;
            f2s[t] = v;                            // reuse as invD cache
        }
        __syncthreads();
        int rr = tid >> 6, o = tid & 63;
        float acc = 0.f;
#pragma unroll 4
        for (int j = rr; j < N; j += 8)
            acc += f2s[j] * g_h[(size_t)(b*N + j)*F + o];
        Dpart[tid] = acc;                          // reuse as reduction scratch
        __syncthreads();
        if (tid < 64) {
            float s = 0.f;
#pragma unroll
            for (int q = 0; q < 8; q++) s += Dpart[q*64 + tid];
            g_c[b*F + tid] = s;
        }
    }
}

// ---------------- D: sparse fp16 gather, half-warp scheme (R9 proven) ----------------
__global__ void k_out(const float* __restrict__ in, const float* __restrict__ bias,
                      float* __restrict__ out) {
    __shared__ float  inv_s[N];                    // 8 KB
    __shared__ float2 pairs_s[16 * MAXNNZ];        // 32 KB (j*16 as int bits, w)
    int tid = threadIdx.x;
    int w = tid >> 5, lane = tid & 31;
    int half = lane >> 4, fl = lane & 15;
    int rowBase = blockIdx.x * 16;
    int b = rowBase >> 11;

    ((float4*)inv_s)[tid] = ((const float4*)(g_invD + b*N))[tid];
    __syncthreads();

    int row = rowBase + w;
    int i = row & (N - 1);
    int npad = (g_nnz[row] + 7) & ~7;
    {
        const float2* __restrict__ pbase = g_pairs + (size_t)row * MAXNNZ;
        float2* ps2 = pairs_s + w * MAXNNZ;
        for (int t = lane; t < npad; t += 32) {
            float2 pr = pbase[t];
            int j = __float_as_int(pr.x);
            ps2[t] = make_float2(__int_as_float(j * 16), pr.y * inv_s[j]);
        }
    }
    __syncwarp();

    const float2* __restrict__ ps2 = pairs_s + w * MAXNNZ;
    const uint2* __restrict__ hh = (const uint2*)(g_hh + (size_t)b*N*F);

    float ax = 0.f, ay = 0.f, az = 0.f, aw = 0.f;
#pragma unroll 1
    for (int k0 = 0; k0 < npad; k0 += 8) {
#pragma unroll
        for (int u = 0; u < 4; u++) {
            float2 pr = ps2[k0 + 2*u + half];
            int j16 = __float_as_int(pr.x);
            uint2 hv = hh[j16 + fl];
            float2 f01 = __half22float2(*(const __half2*)&hv.x);
            float2 f23 = __half22float2(*(const __half2*)&hv.y);
            ax += pr.y * f01.x;
            ay += pr.y * f01.y;
            az += pr.y * f23.x;
            aw += pr.y * f23.y;
        }
    }

    ax += __shfl_xor_sync(0xffffffffu, ax, 16);
    ay += __shfl_xor_sync(0xffffffffu, ay, 16);
    az += __shfl_xor_sync(0xffffffffu, az, 16);
    aw += __shfl_xor_sync(0xffffffffu, aw, 16);

    if (half == 0) {
        int off = row * F + fl * 4;
        float4 cv = ((const float4*)(g_c + b*F))[fl];
        float4 bv = ((const float4*)(bias + i*F))[fl];
        float4 iv = *(const float4*)(in + off);
        float v0 = ax + cv.x + bv.x + iv.x;
        float v1 = ay + cv.y + bv.y + iv.y;
        float v2 = az + cv.z + bv.z + iv.z;
        float v3 = aw + cv.w + bv.w + iv.w;
        float4 res;
        res.x = (v0 > 0.f) ? v0 : expm1f(v0);
        res.y = (v1 > 0.f) ? v1 : expm1f(v1);
        res.z = (v2 > 0.f) ? v2 : expm1f(v2);
        res.w = (v3 > 0.f) ? v3 : expm1f(v3);
        *(float4*)(out + off) = res;
    }
}

// ---------------- launch ----------------
extern "C" void kernel_launch(void* const* d_in, const int* in_sizes, int n_in,
                              void* d_out, int out_size) {
    const float* input = (const float*)d_in[0];
    const float* adj   = (const float*)d_in[1];
    const float* W     = (const float*)d_in[2];
    const float* a1    = (const float*)d_in[3];
    const float* a2    = (const float*)d_in[4];
    const float* bias  = (const float*)d_in[5];
    float* out = (float*)d_out;

    k_hproj<<<BN/8,  512>>>(input, W, a1, a2);
    k_scan <<<BN/16, 512>>>(adj);
    k_out  <<<BN/16, 512>>>(input, bias, out);
}

// round 14
// speedup vs baseline: 1.6628x; 1.6628x over previous
#include <cuda_runtime.h>
#include <cuda_fp16.h>

#define B 8
#define N 2048
#define F 64
#define MAXNNZ 256
#define BN (B*N)  // 16384
#define LRELU_SLOPE 0.2f

// ---- scratch (static device arrays; re-initialized every launch) ----
__device__ float  g_h[BN*F];                       // 4 MB fp32 h (cvec path)
__device__ __half g_hh[BN*F];                      // 2 MB fp16 h (k_out gather path)
__device__ float  g_f1[BN];
__device__ float  g_f2[BN];
__device__ float  g_Dsum[BN];                      // sum of expm1 terms per column
__device__ float  g_invD[BN];
__device__ float  g_c[B*F];                        // per-batch constant row
__device__ int    g_nnz[BN];
__device__ float2 g_pairs[(size_t)BN*MAXNNZ];      // (j as int bits, p), zero-padded to %8

// ---------------- A: h = input@W, 4-col register tile; f1/f2; zero accumulators ------
// block = 512 threads = 32 rows x 16 col-groups(4 cols); grid = BN/32 = 512
__global__ void k_hproj(const float* __restrict__ in, const float* __restrict__ W,
                        const float* __restrict__ a1, const float* __restrict__ a2) {
    __shared__ float4 Ws4[F*16];      // 16 KB: W[f][og*4..og*4+3]
    __shared__ float  a1s[F], a2s[F];
    __shared__ float  ins[32*F];      // 8 KB
    int tid = threadIdx.x;
    int rowBase = blockIdx.x * 32;

    if (blockIdx.x < 32) g_Dsum[blockIdx.x * 512 + tid] = 0.f;
    if (blockIdx.x == 32 && tid < B*F) g_c[tid] = 0.f;

    for (int t = tid; t < F*16; t += 512) Ws4[t] = ((const float4*)W)[t];
    if (tid < F) { a1s[tid] = a1[tid]; a2s[tid] = a2[tid]; }
    ((float4*)ins)[tid] = ((const float4*)(in + rowBase*F))[tid];
    __syncthreads();

    int r = tid >> 4, og = tid & 15;
    const float* insr = ins + r*F;
    float4 acc = make_float4(0.f, 0.f, 0.f, 0.f);
#pragma unroll
    for (int f = 0; f < F; f++) {
        float  iv = insr[f];                       // broadcast LDS
        float4 wv = Ws4[f*16 + og];                // LDS.128, conflict-free
        acc.x += iv*wv.x; acc.y += iv*wv.y;
        acc.z += iv*wv.z; acc.w += iv*wv.w;
    }
    int row = rowBase + r;
    *(float4*)(g_h + (size_t)row*F + og*4) = acc;
    __half2 h01 = __floats2half2_rn(acc.x, acc.y);
    __half2 h23 = __floats2half2_rn(acc.z, acc.w);
    uint2 hp;
    hp.x = *(unsigned*)&h01;
    hp.y = *(unsigned*)&h23;
    *(uint2*)(g_hh + (size_t)row*F + og*4) = hp;

    // f1/f2: per-thread 4-col dot, xor-butterfly over the 16 og-lanes (group-safe)
    float s1 = acc.x*a1s[og*4] + acc.y*a1s[og*4+1] + acc.z*a1s[og*4+2] + acc.w*a1s[og*4+3];
    float s2 = acc.x*a2s[og*4] + acc.y*a2s[og*4+1] + acc.z*a2s[og*4+2] + acc.w*a2s[og*4+3];
#pragma unroll
    for (int m = 8; m; m >>= 1) {
        s1 += __shfl_xor_sync(0xffffffffu, s1, m);
        s2 += __shfl_xor_sync(0xffffffffu, s2, m);
    }
    if (og == 0) { g_f1[row] = s1; g_f2[row] = s2; }
}

// ---------------- B: two-phase scan (R12 proven) ----------------
// block = 512 threads = 16 warps = 16 rows; grid = BN/16.
__global__ void k_scan(const float* __restrict__ adj) {
    __shared__ float Dpart[N];        // 8 KB
    __shared__ float f2s[N];          // 8 KB
    int tid = threadIdx.x;
    int b  = blockIdx.x >> 7;
    int i0 = (blockIdx.x & 127) * 16;

    for (int t = tid; t < N; t += 512) Dpart[t] = 0.f;
    for (int t = tid; t < N; t += 512) f2s[t] = g_f2[b*N + t];
    __syncthreads();

    int w = tid >> 5, lane = tid & 31;
    int row = b*N + i0 + w;
    float f1i = g_f1[row];
    const float4* __restrict__ arow = (const float4*)(adj + (size_t)row * N);
    float2* pbase = g_pairs + (size_t)row * MAXNNZ;
    unsigned lmask = (1u << lane) - 1u;

    unsigned long long m64 = 0ull;
    float4 a0 = arow[lane], a1 = arow[lane + 32];
#pragma unroll 1
    for (int it = 0; it < 16; it += 2) {
        float4 n0, n1;
        if (it < 14) {
            n0 = arow[(it + 2)*32 + lane];
            n1 = arow[(it + 3)*32 + lane];
        }
        unsigned mk0 = (a0.x != 0.f ? 1u : 0u) | (a0.y != 0.f ? 2u : 0u)
                     | (a0.z != 0.f ? 4u : 0u) | (a0.w != 0.f ? 8u : 0u);
        unsigned mk1 = (a1.x != 0.f ? 1u : 0u) | (a1.y != 0.f ? 2u : 0u)
                     | (a1.z != 0.f ? 4u : 0u) | (a1.w != 0.f ? 8u : 0u);
        m64 |= ((unsigned long long)(mk0 | (mk1 << 4))) << (4*it);
        a0 = n0; a1 = n1;
    }
    int cnt = __popcll(m64);

    int base = 0, total = 0;
#pragma unroll
    for (int bit = 0; bit < 7; bit++) {
        unsigned mm = __ballot_sync(0xffffffffu, (cnt >> bit) & 1);
        base  += __popc(mm & lmask) << bit;
        total += __popc(mm) << bit;
    }

    while (m64) {
        int bitp = __ffsll(m64) - 1;
        m64 &= m64 - 1;
        int it = bitp >> 2, k = bitp & 3;
        int j = ((it*32 + lane) << 2) + k;
        float e = f1i + f2s[j];
        e = (e >= 0.f) ? e : LRELU_SLOPE * e;
        float p = __expf(e) - 1.f;
        if (base < MAXNNZ)
            pbase[base] = make_float2(__int_as_float(j), p);
        base++;
        atomicAdd(&Dpart[j], p);
    }

    int nnz = min(total, MAXNNZ);
    if (lane == 0) g_nnz[row] = nnz;
    int npad = (nnz + 7) & ~7;
    if (nnz + lane < npad) pbase[nnz + lane] = make_float2(0.f, 0.f);

    __syncthreads();
    for (int tt = tid; tt < N; tt += 512) atomicAdd(&g_Dsum[b*N + tt], Dpart[tt]);
}

// ---------------- C: invD = 1/(N+Dsum); c[b,o] += sum_j invD[j]*h[j,o] ----------------
__global__ void k_cvec() {
    __shared__ float inv_s[64];
    __shared__ float part[512];
    int tid = threadIdx.x;
    int b  = blockIdx.x >> 5;
    int j0 = (blockIdx.x & 31) * 64;

    if (tid < 64) {
        float v = 1.f / ((float)N + g_Dsum[b*N + j0 + tid]);
        g_invD[b*N + j0 + tid] = v;
        inv_s[tid] = v;
    }
    __syncthreads();

    int r = tid >> 6, o = tid & 63;
    float acc = 0.f;
#pragma unroll
    for (int q = 0; q < 8; q++) {
        int jj = q*8 + r;
        acc += inv_s[jj] * g_h[(size_t)(b*N + j0 + jj)*F + o];
    }
    part[tid] = acc;
    __syncthreads();
    if (tid < 64) {
        float s = 0.f;
#pragma unroll
        for (int q = 0; q < 8; q++) s += part[q*64 + tid];
        atomicAdd(&g_c[b*F + tid], s);
    }
}

// ---------------- D: sparse fp16 gather, half-warp scheme (R9 proven) ----------------
__global__ void k_out(const float* __restrict__ in, const float* __restrict__ bias,
                      float* __restrict__ out) {
    __shared__ float  inv_s[N];                    // 8 KB
    __shared__ float2 pairs_s[16 * MAXNNZ];        // 32 KB (j*16 as int bits, w)
    int tid = threadIdx.x;
    int w = tid >> 5, lane = tid & 31;
    int half = lane >> 4, fl = lane & 15;
    int rowBase = blockIdx.x * 16;
    int b = rowBase >> 11;

    ((float4*)inv_s)[tid] = ((const float4*)(g_invD + b*N))[tid];
    __syncthreads();

    int row = rowBase + w;
    int i = row & (N - 1);
    int npad = (g_nnz[row] + 7) & ~7;
    {
        const float2* __restrict__ pbase = g_pairs + (size_t)row * MAXNNZ;
        float2* ps2 = pairs_s + w * MAXNNZ;
        for (int t = lane; t < npad; t += 32) {
            float2 pr = pbase[t];
            int j = __float_as_int(pr.x);
            ps2[t] = make_float2(__int_as_float(j * 16), pr.y * inv_s[j]);
        }
    }
    __syncwarp();

    const float2* __restrict__ ps2 = pairs_s + w * MAXNNZ;
    const uint2* __restrict__ hh = (const uint2*)(g_hh + (size_t)b*N*F);

    float ax = 0.f, ay = 0.f, az = 0.f, aw = 0.f;
#pragma unroll 1
    for (int k0 = 0; k0 < npad; k0 += 8) {
#pragma unroll
        for (int u = 0; u < 4; u++) {
            float2 pr = ps2[k0 + 2*u + half];
            int j16 = __float_as_int(pr.x);
            uint2 hv = hh[j16 + fl];
            float2 f01 = __half22float2(*(const __half2*)&hv.x);
            float2 f23 = __half22float2(*(const __half2*)&hv.y);
            ax += pr.y * f01.x;
            ay += pr.y * f01.y;
            az += pr.y * f23.x;
            aw += pr.y * f23.y;
        }
    }

    ax += __shfl_xor_sync(0xffffffffu, ax, 16);
    ay += __shfl_xor_sync(0xffffffffu, ay, 16);
    az += __shfl_xor_sync(0xffffffffu, az, 16);
    aw += __shfl_xor_sync(0xffffffffu, aw, 16);

    if (half == 0) {
        int off = row * F + fl * 4;
        float4 cv = ((const float4*)(g_c + b*F))[fl];
        float4 bv = ((const float4*)(bias + i*F))[fl];
        float4 iv = *(const float4*)(in + off);
        float v0 = ax + cv.x + bv.x + iv.x;
        float v1 = ay + cv.y + bv.y + iv.y;
        float v2 = az + cv.z + bv.z + iv.z;
        float v3 = aw + cv.w + bv.w + iv.w;
        float4 res;
        res.x = (v0 > 0.f) ? v0 : expm1f(v0);
        res.y = (v1 > 0.f) ? v1 : expm1f(v1);
        res.z = (v2 > 0.f) ? v2 : expm1f(v2);
        res.w = (v3 > 0.f) ? v3 : expm1f(v3);
        *(float4*)(out + off) = res;
    }
}

// ---------------- launch ----------------
extern "C" void kernel_launch(void* const* d_in, const int* in_sizes, int n_in,
                              void* d_out, int out_size) {
    const float* input = (const float*)d_in[0];
    const float* adj   = (const float*)d_in[1];
    const float* W     = (const float*)d_in[2];
    const float* a1    = (const float*)d_in[3];
    const float* a2    = (const float*)d_in[4];
    const float* bias  = (const float*)d_in[5];
    float* out = (float*)d_out;

    k_hproj<<<BN/32, 512>>>(input, W, a1, a2);
    k_scan <<<BN/16, 512>>>(adj);
    k_cvec <<<B*32,  512>>>();
    k_out  <<<BN/16, 512>>>(input, bias, out);
}

// round 16
// speedup vs baseline: 1.6678x; 1.0030x over previous
#include <cuda_runtime.h>
#include <cuda_fp16.h>

#define B 8
#define N 2048
#define F 64
#define MAXNNZ 256
#define BN (B*N)  // 16384
#define LRELU_SLOPE 0.2f

// ---- scratch (static device arrays; re-initialized every launch) ----
__device__ float  g_h[BN*F];                       // 4 MB fp32 h (cvec path)
__device__ __half g_hh[BN*F];                      // 2 MB fp16 h (k_out gather path)
__device__ float  g_f1[BN];
__device__ float  g_f2[BN];
__device__ float  g_Dsum[BN];                      // sum of expm1 terms per column
__device__ float  g_invD[BN];
__device__ float  g_c[B*F];                        // per-batch constant row
__device__ int    g_nnz[BN];
__device__ float2 g_pairs[(size_t)BN*MAXNNZ];      // (j as int bits, p), zero-padded to %16

// ---------------- A: h = input@W, 4-col register tile; f1/f2; zero accumulators ------
// block = 512 threads = 32 rows x 16 col-groups(4 cols); grid = BN/32 = 512
__global__ void k_hproj(const float* __restrict__ in, const float* __restrict__ W,
                        const float* __restrict__ a1, const float* __restrict__ a2) {
    __shared__ float4 Ws4[F*16];      // 16 KB: W[f][og*4..og*4+3]
    __shared__ float  a1s[F], a2s[F];
    __shared__ float  ins[32*F];      // 8 KB
    int tid = threadIdx.x;
    int rowBase = blockIdx.x * 32;

    if (blockIdx.x < 32) g_Dsum[blockIdx.x * 512 + tid] = 0.f;
    if (blockIdx.x == 32 && tid < B*F) g_c[tid] = 0.f;

    for (int t = tid; t < F*16; t += 512) Ws4[t] = ((const float4*)W)[t];
    if (tid < F) { a1s[tid] = a1[tid]; a2s[tid] = a2[tid]; }
    ((float4*)ins)[tid] = ((const float4*)(in + rowBase*F))[tid];
    __syncthreads();

    int r = tid >> 4, og = tid & 15;
    const float* insr = ins + r*F;
    float4 acc = make_float4(0.f, 0.f, 0.f, 0.f);
#pragma unroll
    for (int f = 0; f < F; f++) {
        float  iv = insr[f];                       // broadcast LDS
        float4 wv = Ws4[f*16 + og];                // LDS.128, conflict-free
        acc.x += iv*wv.x; acc.y += iv*wv.y;
        acc.z += iv*wv.z; acc.w += iv*wv.w;
    }
    int row = rowBase + r;
    *(float4*)(g_h + (size_t)row*F + og*4) = acc;
    __half2 h01 = __floats2half2_rn(acc.x, acc.y);
    __half2 h23 = __floats2half2_rn(acc.z, acc.w);
    uint2 hp;
    hp.x = *(unsigned*)&h01;
    hp.y = *(unsigned*)&h23;
    *(uint2*)(g_hh + (size_t)row*F + og*4) = hp;

    // f1/f2: per-thread 4-col dot, xor-butterfly over the 16 og-lanes (group-safe)
    float s1 = acc.x*a1s[og*4] + acc.y*a1s[og*4+1] + acc.z*a1s[og*4+2] + acc.w*a1s[og*4+3];
    float s2 = acc.x*a2s[og*4] + acc.y*a2s[og*4+1] + acc.z*a2s[og*4+2] + acc.w*a2s[og*4+3];
#pragma unroll
    for (int m = 8; m; m >>= 1) {
        s1 += __shfl_xor_sync(0xffffffffu, s1, m);
        s2 += __shfl_xor_sync(0xffffffffu, s2, m);
    }
    if (og == 0) { g_f1[row] = s1; g_f2[row] = s2; }
}

// ---------------- B: two-phase scan (R12 proven; padding now %16) ----------------
// block = 512 threads = 16 warps = 16 rows; grid = BN/16.
__global__ void k_scan(const float* __restrict__ adj) {
    __shared__ float Dpart[N];        // 8 KB
    __shared__ float f2s[N];          // 8 KB
    int tid = threadIdx.x;
    int b  = blockIdx.x >> 7;
    int i0 = (blockIdx.x & 127) * 16;

    for (int t = tid; t < N; t += 512) Dpart[t] = 0.f;
    for (int t = tid; t < N; t += 512) f2s[t] = g_f2[b*N + t];
    __syncthreads();

    int w = tid >> 5, lane = tid & 31;
    int row = b*N + i0 + w;
    float f1i = g_f1[row];
    const float4* __restrict__ arow = (const float4*)(adj + (size_t)row * N);
    float2* pbase = g_pairs + (size_t)row * MAXNNZ;
    unsigned lmask = (1u << lane) - 1u;

    unsigned long long m64 = 0ull;
    float4 a0 = arow[lane], a1 = arow[lane + 32];
#pragma unroll 1
    for (int it = 0; it < 16; it += 2) {
        float4 n0, n1;
        if (it < 14) {
            n0 = arow[(it + 2)*32 + lane];
            n1 = arow[(it + 3)*32 + lane];
        }
        unsigned mk0 = (a0.x != 0.f ? 1u : 0u) | (a0.y != 0.f ? 2u : 0u)
                     | (a0.z != 0.f ? 4u : 0u) | (a0.w != 0.f ? 8u : 0u);
        unsigned mk1 = (a1.x != 0.f ? 1u : 0u) | (a1.y != 0.f ? 2u : 0u)
                     | (a1.z != 0.f ? 4u : 0u) | (a1.w != 0.f ? 8u : 0u);
        m64 |= ((unsigned long long)(mk0 | (mk1 << 4))) << (4*it);
        a0 = n0; a1 = n1;
    }
    int cnt = __popcll(m64);

    int base = 0, total = 0;
#pragma unroll
    for (int bit = 0; bit < 7; bit++) {
        unsigned mm = __ballot_sync(0xffffffffu, (cnt >> bit) & 1);
        base  += __popc(mm & lmask) << bit;
        total += __popc(mm) << bit;
    }

    while (m64) {
        int bitp = __ffsll(m64) - 1;
        m64 &= m64 - 1;
        int it = bitp >> 2, k = bitp & 3;
        int j = ((it*32 + lane) << 2) + k;
        float e = f1i + f2s[j];
        e = (e >= 0.f) ? e : LRELU_SLOPE * e;
        float p = __expf(e) - 1.f;
        if (base < MAXNNZ)
            pbase[base] = make_float2(__int_as_float(j), p);
        base++;
        atomicAdd(&Dpart[j], p);
    }

    int nnz = min(total, MAXNNZ);
    if (lane == 0) g_nnz[row] = nnz;
    int npad = (nnz + 15) & ~15;                   // pad to %16 for k_out unroll-8
    if (npad > MAXNNZ) npad = MAXNNZ;
    if (nnz + lane < npad) pbase[nnz + lane] = make_float2(0.f, 0.f);

    __syncthreads();
    for (int tt = tid; tt < N; tt += 512) atomicAdd(&g_Dsum[b*N + tt], Dpart[tt]);
}

// ---------------- C: invD = 1/(N+Dsum); c[b,o] += sum_j invD[j]*h[j,o] ----------------
__global__ void k_cvec() {
    __shared__ float inv_s[64];
    __shared__ float part[512];
    int tid = threadIdx.x;
    int b  = blockIdx.x >> 5;
    int j0 = (blockIdx.x & 31) * 64;

    if (tid < 64) {
        float v = 1.f / ((float)N + g_Dsum[b*N + j0 + tid]);
        g_invD[b*N + j0 + tid] = v;
        inv_s[tid] = v;
    }
    __syncthreads();

    int r = tid >> 6, o = tid & 63;
    float acc = 0.f;
#pragma unroll
    for (int q = 0; q < 8; q++) {
        int jj = q*8 + r;
        acc += inv_s[jj] * g_h[(size_t)(b*N + j0 + jj)*F + o];
    }
    part[tid] = acc;
    __syncthreads();
    if (tid < 64) {
        float s = 0.f;
#pragma unroll
        for (int q = 0; q < 8; q++) s += part[q*64 + tid];
        atomicAdd(&g_c[b*F + tid], s);
    }
}

// ---------------- D: sparse fp16 gather, half-warp scheme, 8-deep window ----------
// block = 512 threads = 16 warps = 16 rows (same batch); grid = BN/16.
// Lanes 0-15 even pairs, 16-31 odd; each lane loads uint2 (4 fp16) = 128B row.
__global__ void k_out(const float* __restrict__ in, const float* __restrict__ bias,
                      float* __restrict__ out) {
    __shared__ float  inv_s[N];                    // 8 KB
    __shared__ float2 pairs_s[16 * MAXNNZ];        // 32 KB (j*16 as int bits, w)
    int tid = threadIdx.x;
    int w = tid >> 5, lane = tid & 31;
    int half = lane >> 4, fl = lane & 15;
    int rowBase = blockIdx.x * 16;
    int b = rowBase >> 11;

    ((float4*)inv_s)[tid] = ((const float4*)(g_invD + b*N))[tid];
    __syncthreads();

    int row = rowBase + w;
    int i = row & (N - 1);
    int npad = (g_nnz[row] + 15) & ~15;
    if (npad > MAXNNZ) npad = MAXNNZ;
    {
        const float2* __restrict__ pbase = g_pairs + (size_t)row * MAXNNZ;
        float2* ps2w = pairs_s + w * MAXNNZ;
        for (int t = lane; t < npad; t += 32) {
            float2 pr = pbase[t];
            int j = __float_as_int(pr.x);
            ps2w[t] = make_float2(__int_as_float(j * 16), pr.y * inv_s[j]);
        }
    }
    __syncwarp();

    const float2* __restrict__ ps2 = pairs_s + w * MAXNNZ;
    const uint2* __restrict__ hh = (const uint2*)(g_hh + (size_t)b*N*F);

    float ax = 0.f, ay = 0.f, az = 0.f, aw = 0.f;
#pragma unroll 1
    for (int k0 = 0; k0 < npad; k0 += 16) {
#pragma unroll
        for (int u = 0; u < 8; u++) {
            float2 pr = ps2[k0 + 2*u + half];      // broadcast LDS.64 per half-warp
            int j16 = __float_as_int(pr.x);
            uint2 hv = hh[j16 + fl];               // 16 lanes x 8B = 128B row
            float2 f01 = __half22float2(*(const __half2*)&hv.x);
            float2 f23 = __half22float2(*(const __half2*)&hv.y);
            ax += pr.y * f01.x;
            ay += pr.y * f01.y;
            az += pr.y * f23.x;
            aw += pr.y * f23.y;
        }
    }

    ax += __shfl_xor_sync(0xffffffffu, ax, 16);
    ay += __shfl_xor_sync(0xffffffffu, ay, 16);
    az += __shfl_xor_sync(0xffffffffu, az, 16);
    aw += __shfl_xor_sync(0xffffffffu, aw, 16);

    if (half == 0) {
        int off = row * F + fl * 4;
        float4 cv = ((const float4*)(g_c + b*F))[fl];
        float4 bv = ((const float4*)(bias + i*F))[fl];
        float4 iv = *(const float4*)(in + off);
        float v0 = ax + cv.x + bv.x + iv.x;
        float v1 = ay + cv.y + bv.y + iv.y;
        float v2 = az + cv.z + bv.z + iv.z;
        float v3 = aw + cv.w + bv.w + iv.w;
        float4 res;
        res.x = (v0 > 0.f) ? v0 : expm1f(v0);
        res.y = (v1 > 0.f) ? v1 : expm1f(v1);
        res.z = (v2 > 0.f) ? v2 : expm1f(v2);
        res.w = (v3 > 0.f) ? v3 : expm1f(v3);
        *(float4*)(out + off) = res;
    }
}

// ---------------- launch ----------------
extern "C" void kernel_launch(void* const* d_in, const int* in_sizes, int n_in,
                              void* d_out, int out_size) {
    const float* input = (const float*)d_in[0];
    const float* adj   = (const float*)d_in[1];
    const float* W     = (const float*)d_in[2];
    const float* a1    = (const float*)d_in[3];
    const float* a2    = (const float*)d_in[4];
    const float* bias  = (const float*)d_in[5];
    float* out = (float*)d_out;

    k_hproj<<<BN/32, 512>>>(input, W, a1, a2);
    k_scan <<<BN/16, 512>>>(adj);
    k_cvec <<<B*32,  512>>>();
    k_out  <<<BN/16, 512>>>(input, bias, out);
}

// round 17
// speedup vs baseline: 1.7599x; 1.0552x over previous
#include <cuda_runtime.h>
#include <cuda_fp16.h>

#define B 8
#define N 2048
#define F 64
#define MAXNNZ 256
#define BN (B*N)  // 16384
#define LRELU_SLOPE 0.2f

// ---- scratch (static device arrays; re-initialized every launch) ----
__device__ float  g_h[BN*F];                       // 4 MB fp32 h (cvec path)
__device__ __half g_hh[BN*F];                      // 2 MB fp16 h (k_out gather path)
__device__ float  g_f1[BN];
__device__ float  g_f2[BN];
__device__ float  g_Dsum[BN];                      // sum of expm1 terms per column
__device__ float  g_invD[BN];
__device__ float  g_c[B*F];                        // per-batch constant row
__device__ int    g_nnz[BN];
__device__ float2 g_pairs[(size_t)BN*MAXNNZ];      // (j as int bits, p), zero-padded to %16

// ---------------- A: h = input@W, 4x4 register tile; f1/f2; zero accumulators --------
// block = 256 threads = 16 row-quads x 16 col-groups; 64 rows/block; grid = BN/64 = 256
__global__ void k_hproj(const float* __restrict__ in, const float* __restrict__ W,
                        const float* __restrict__ a1, const float* __restrict__ a2) {
    __shared__ float4 Ws4[F*16];      // 16 KB: W[f][og*4..og*4+3]
    __shared__ float  a1s[F], a2s[F];
    __shared__ float  ins[64*F];      // 16 KB
    int tid = threadIdx.x;
    int rowBase = blockIdx.x * 64;

    if (blockIdx.x < 64) g_Dsum[blockIdx.x * 256 + tid] = 0.f;
    if (blockIdx.x == 64) { g_c[tid] = 0.f; g_c[tid + 256] = 0.f; }

    for (int t = tid; t < F*16; t += 256) Ws4[t] = ((const float4*)W)[t];
    if (tid < F) { a1s[tid] = a1[tid]; a2s[tid] = a2[tid]; }
    for (int t = tid; t < 64*F/4; t += 256)
        ((float4*)ins)[t] = ((const float4*)(in + rowBase*F))[t];
    __syncthreads();

    int rq = tid >> 4, og = tid & 15;              // rows rq*4..rq*4+3, cols og*4..og*4+3
    const float* i0 = ins + (rq*4 + 0)*F;
    const float* i1 = ins + (rq*4 + 1)*F;
    const float* i2 = ins + (rq*4 + 2)*F;
    const float* i3 = ins + (rq*4 + 3)*F;
    float4 c0 = make_float4(0.f,0.f,0.f,0.f), c1 = c0, c2 = c0, c3 = c0;
#pragma unroll 8
    for (int f = 0; f < F; f++) {
        float4 wv = Ws4[f*16 + og];                // LDS.128 feeds 16 FFMA
        float v0 = i0[f], v1 = i1[f], v2 = i2[f], v3 = i3[f];
        c0.x += v0*wv.x; c0.y += v0*wv.y; c0.z += v0*wv.z; c0.w += v0*wv.w;
        c1.x += v1*wv.x; c1.y += v1*wv.y; c1.z += v1*wv.z; c1.w += v1*wv.w;
        c2.x += v2*wv.x; c2.y += v2*wv.y; c2.z += v2*wv.z; c2.w += v2*wv.w;
        c3.x += v3*wv.x; c3.y += v3*wv.y; c3.z += v3*wv.z; c3.w += v3*wv.w;
    }

    float a1x = a1s[og*4], a1y = a1s[og*4+1], a1z = a1s[og*4+2], a1w = a1s[og*4+3];
    float a2x = a2s[og*4], a2y = a2s[og*4+1], a2z = a2s[og*4+2], a2w = a2s[og*4+3];
    float s1r[4], s2r[4];
#pragma unroll
    for (int r = 0; r < 4; r++) {
        float4 acc = (r==0) ? c0 : (r==1) ? c1 : (r==2) ? c2 : c3;
        int row = rowBase + rq*4 + r;
        *(float4*)(g_h + (size_t)row*F + og*4) = acc;
        __half2 h01 = __floats2half2_rn(acc.x, acc.y);
        __half2 h23 = __floats2half2_rn(acc.z, acc.w);
        uint2 hp;
        hp.x = *(unsigned*)&h01;
        hp.y = *(unsigned*)&h23;
        *(uint2*)(g_hh + (size_t)row*F + og*4) = hp;
        s1r[r] = acc.x*a1x + acc.y*a1y + acc.z*a1z + acc.w*a1w;
        s2r[r] = acc.x*a2x + acc.y*a2y + acc.z*a2z + acc.w*a2w;
    }
#pragma unroll
    for (int m = 1; m <= 8; m <<= 1) {
#pragma unroll
        for (int r = 0; r < 4; r++) {
            s1r[r] += __shfl_xor_sync(0xffffffffu, s1r[r], m);
            s2r[r] += __shfl_xor_sync(0xffffffffu, s2r[r], m);
        }
    }
    if (og == 0) {
#pragma unroll
        for (int r = 0; r < 4; r++) {
            g_f1[rowBase + rq*4 + r] = s1r[r];
            g_f2[rowBase + rq*4 + r] = s2r[r];
        }
    }
}

// ---------------- B: two-phase scan (R16 proven, byte-identical) ----------------
__global__ void k_scan(const float* __restrict__ adj) {
    __shared__ float Dpart[N];        // 8 KB
    __shared__ float f2s[N];          // 8 KB
    int tid = threadIdx.x;
    int b  = blockIdx.x >> 7;
    int i0 = (blockIdx.x & 127) * 16;

    for (int t = tid; t < N; t += 512) Dpart[t] = 0.f;
    for (int t = tid; t < N; t += 512) f2s[t] = g_f2[b*N + t];
    __syncthreads();

    int w = tid >> 5, lane = tid & 31;
    int row = b*N + i0 + w;
    float f1i = g_f1[row];
    const float4* __restrict__ arow = (const float4*)(adj + (size_t)row * N);
    float2* pbase = g_pairs + (size_t)row * MAXNNZ;
    unsigned lmask = (1u << lane) - 1u;

    unsigned long long m64 = 0ull;
    float4 a0 = arow[lane], a1 = arow[lane + 32];
#pragma unroll 1
    for (int it = 0; it < 16; it += 2) {
        float4 n0, n1;
        if (it < 14) {
            n0 = arow[(it + 2)*32 + lane];
            n1 = arow[(it + 3)*32 + lane];
        }
        unsigned mk0 = (a0.x != 0.f ? 1u : 0u) | (a0.y != 0.f ? 2u : 0u)
                     | (a0.z != 0.f ? 4u : 0u) | (a0.w != 0.f ? 8u : 0u);
        unsigned mk1 = (a1.x != 0.f ? 1u : 0u) | (a1.y != 0.f ? 2u : 0u)
                     | (a1.z != 0.f ? 4u : 0u) | (a1.w != 0.f ? 8u : 0u);
        m64 |= ((unsigned long long)(mk0 | (mk1 << 4))) << (4*it);
        a0 = n0; a1 = n1;
    }
    int cnt = __popcll(m64);

    int base = 0, total = 0;
#pragma unroll
    for (int bit = 0; bit < 7; bit++) {
        unsigned mm = __ballot_sync(0xffffffffu, (cnt >> bit) & 1);
        base  += __popc(mm & lmask) << bit;
        total += __popc(mm) << bit;
    }

    while (m64) {
        int bitp = __ffsll(m64) - 1;
        m64 &= m64 - 1;
        int it = bitp >> 2, k = bitp & 3;
        int j = ((it*32 + lane) << 2) + k;
        float e = f1i + f2s[j];
        e = (e >= 0.f) ? e : LRELU_SLOPE * e;
        float p = __expf(e) - 1.f;
        if (base < MAXNNZ)
            pbase[base] = make_float2(__int_as_float(j), p);
        base++;
        atomicAdd(&Dpart[j], p);
    }

    int nnz = min(total, MAXNNZ);
    if (lane == 0) g_nnz[row] = nnz;
    int npad = (nnz + 15) & ~15;
    if (npad > MAXNNZ) npad = MAXNNZ;
    if (nnz + lane < npad) pbase[nnz + lane] = make_float2(0.f, 0.f);

    __syncthreads();
    for (int tt = tid; tt < N; tt += 512) atomicAdd(&g_Dsum[b*N + tt], Dpart[tt]);
}

// ---------------- C: invD = 1/(N+Dsum); c[b,o] += sum_j invD[j]*h[j,o] ----------------
__global__ void k_cvec() {
    __shared__ float inv_s[64];
    __shared__ float part[512];
    int tid = threadIdx.x;
    int b  = blockIdx.x >> 5;
    int j0 = (blockIdx.x & 31) * 64;

    if (tid < 64) {
        float v = 1.f / ((float)N + g_Dsum[b*N + j0 + tid]);
        g_invD[b*N + j0 + tid] = v;
        inv_s[tid] = v;
    }
    __syncthreads();

    int r = tid >> 6, o = tid & 63;
    float acc = 0.f;
#pragma unroll
    for (int q = 0; q < 8; q++) {
        int jj = q*8 + r;
        acc += inv_s[jj] * g_h[(size_t)(b*N + j0 + jj)*F + o];
    }
    part[tid] = acc;
    __syncthreads();
    if (tid < 64) {
        float s = 0.f;
#pragma unroll
        for (int q = 0; q < 8; q++) s += part[q*64 + tid];
        atomicAdd(&g_c[b*F + tid], s);
    }
}

// ---------------- D: sparse fp16 gather, half-warp scheme, 8-deep window (R16) ------
__global__ void k_out(const float* __restrict__ in, const float* __restrict__ bias,
                      float* __restrict__ out) {
    __shared__ float  inv_s[N];                    // 8 KB
    __shared__ float2 pairs_s[16 * MAXNNZ];        // 32 KB (j*16 as int bits, w)
    int tid = threadIdx.x;
    int w = tid >> 5, lane = tid & 31;
    int half = lane >> 4, fl = lane & 15;
    int rowBase = blockIdx.x * 16;
    int b = rowBase >> 11;

    ((float4*)inv_s)[tid] = ((const float4*)(g_invD + b*N))[tid];
    __syncthreads();

    int row = rowBase + w;
    int i = row & (N - 1);
    int npad = (g_nnz[row] + 15) & ~15;
    if (npad > MAXNNZ) npad = MAXNNZ;
    {
        const float2* __restrict__ pbase = g_pairs + (size_t)row * MAXNNZ;
        float2* ps2w = pairs_s + w * MAXNNZ;
        for (int t = lane; t < npad; t += 32) {
            float2 pr = pbase[t];
            int j = __float_as_int(pr.x);
            ps2w[t] = make_float2(__int_as_float(j * 16), pr.y * inv_s[j]);
        }
    }
    __syncwarp();

    const float2* __restrict__ ps2 = pairs_s + w * MAXNNZ;
    const uint2* __restrict__ hh = (const uint2*)(g_hh + (size_t)b*N*F);

    float ax = 0.f, ay = 0.f, az = 0.f, aw = 0.f;
#pragma unroll 1
    for (int k0 = 0; k0 < npad; k0 += 16) {
#pragma unroll
        for (int u = 0; u < 8; u++) {
            float2 pr = ps2[k0 + 2*u + half];      // broadcast LDS.64 per half-warp
            int j16 = __float_as_int(pr.x);
            uint2 hv = hh[j16 + fl];               // 16 lanes x 8B = 128B row
            float2 f01 = __half22float2(*(const __half2*)&hv.x);
            float2 f23 = __half22float2(*(const __half2*)&hv.y);
            ax += pr.y * f01.x;
            ay += pr.y * f01.y;
            az += pr.y * f23.x;
            aw += pr.y * f23.y;
        }
    }

    ax += __shfl_xor_sync(0xffffffffu, ax, 16);
    ay += __shfl_xor_sync(0xffffffffu, ay, 16);
    az += __shfl_xor_sync(0xffffffffu, az, 16);
    aw += __shfl_xor_sync(0xffffffffu, aw, 16);

    if (half == 0) {
        int off = row * F + fl * 4;
        float4 cv = ((const float4*)(g_c + b*F))[fl];
        float4 bv = ((const float4*)(bias + i*F))[fl];
        float4 iv = *(const float4*)(in + off);
        float v0 = ax + cv.x + bv.x + iv.x;
        float v1 = ay + cv.y + bv.y + iv.y;
        float v2 = az + cv.z + bv.z + iv.z;
        float v3 = aw + cv.w + bv.w + iv.w;
        float4 res;
        res.x = (v0 > 0.f) ? v0 : expm1f(v0);
        res.y = (v1 > 0.f) ? v1 : expm1f(v1);
        res.z = (v2 > 0.f) ? v2 : expm1f(v2);
        res.w = (v3 > 0.f) ? v3 : expm1f(v3);
        *(float4*)(out + off) = res;
    }
}

// ---------------- launch ----------------
extern "C" void kernel_launch(void* const* d_in, const int* in_sizes, int n_in,
                              void* d_out, int out_size) {
    const float* input = (const float*)d_in[0];
    const float* adj   = (const float*)d_in[1];
    const float* W     = (const float*)d_in[2];
    const float* a1    = (const float*)d_in[3];
    const float* a2    = (const float*)d_in[4];
    const float* bias  = (const float*)d_in[5];
    float* out = (float*)d_out;

    k_hproj<<<BN/64, 256>>>(input, W, a1, a2);
    k_scan <<<BN/16, 512>>>(adj);
    k_cvec <<<B*32,  512>>>();
    k_out  <<<BN/16, 512>>>(input, bias, out);
}